// round 16
// baseline (speedup 1.0000x reference)
#include <cuda_runtime.h>
#include <cuda_bf16.h>
#include <math.h>
#include <stdint.h>

#define BATCH 4096
#define FDIM  512
#define NCLS  1000
#define MARGIN 0.3f
#define LAMBDA 0.01f
#define EPSV   1e-12f
#define NJT2  16         // CE partials per row: 8 j-tiles x 2 warp-halves

#define BM 128
#define BN 128

// ---- bf16 tiling (shared by triplet + CE) ----
#define BKT 64
#define NCHT (FDIM / BKT)                // 8
#define SSTRW 36                         // words per bf16 row (64 bf16 = 32 words + 4 pad)
#define TSTAGE_BYTES (256 * SSTRW * 4)   // 36864
#define PSTAGES 3
#define TDYN_BYTES   (PSTAGES * TSTAGE_BYTES)  // 110592 (2 CTAs = 216KB <= 228KB/SM)

#define NTILE (BATCH / BM)               // 32
#define NTRI  (NTILE * (NTILE + 1) / 2)  // 528

// ---------------- device scratch ----------------
__device__ float        g_sq[BATCH];
__device__ int          g_lab[BATCH];
__device__ unsigned int g_ap[BATCH];
__device__ unsigned int g_an[BATCH];
__device__ float        g_cent[BATCH];
__device__ float        g_pm[BATCH][NJT2];
__device__ float        g_ps[BATCH][NJT2];
__device__ float        g_ref[BATCH];
__device__ int          g_labmode;
__device__ __align__(16) uint4 g_ebf4[BATCH * FDIM / 8];   // E in bf16 (4 MB)
__device__ __align__(16) uint4 g_wbf4[NCLS * FDIM / 8];    // W in bf16 (1 MB)

// ---------------- helpers ----------------
__device__ __forceinline__ uint32_t smem_u32(const void* p) {
    uint32_t a;
    asm("{ .reg .u64 t; cvta.to.shared.u64 t, %1; cvt.u32.u64 %0, t; }" : "=r"(a) : "l"(p));
    return a;
}
__device__ __forceinline__ void cp16(uint32_t dst, const void* src) {
    asm volatile("cp.async.cg.shared.global [%0], [%1], 16;" :: "r"(dst), "l"(src));
}
__device__ __forceinline__ void cp_commit() {
    asm volatile("cp.async.commit_group;" ::: "memory");
}
template<int N> __device__ __forceinline__ void cp_wait() {
    asm volatile("cp.async.wait_group %0;" :: "n"(N) : "memory");
}
__device__ __forceinline__ void mma_bf16(float* c, const uint32_t* a, uint32_t b0, uint32_t b1) {
    asm volatile(
        "mma.sync.aligned.m16n8k16.row.col.f32.bf16.bf16.f32 "
        "{%0,%1,%2,%3}, {%4,%5,%6,%7}, {%8,%9}, {%0,%1,%2,%3};"
        : "+f"(c[0]), "+f"(c[1]), "+f"(c[2]), "+f"(c[3])
        : "r"(a[0]), "r"(a[1]), "r"(a[2]), "r"(a[3]), "r"(b0), "r"(b1));
}
__device__ __forceinline__ void ldsm_x4(uint32_t& r0, uint32_t& r1, uint32_t& r2, uint32_t& r3,
                                        uint32_t addr) {
    asm volatile("ldmatrix.sync.aligned.m8n8.x4.shared.b16 {%0,%1,%2,%3}, [%4];"
        : "=r"(r0), "=r"(r1), "=r"(r2), "=r"(r3) : "r"(addr));
}

// ---------------- fused label-detect (block 0) + W -> bf16 convert ----------------
__global__ void detect_wconv_kernel(const long long* __restrict__ lab64,
                                    const float* __restrict__ W) {
    if (blockIdx.x == 0) {
        __shared__ int bad;
        if (threadIdx.x == 0) bad = 0;
        __syncthreads();
        int mybad = 0;
        for (int i = threadIdx.x; i < 2048; i += blockDim.x) {
            long long v = lab64[i];
            if (v < 0 || v >= NCLS) mybad = 1;
        }
        if (mybad) atomicOr(&bad, 1);
        __syncthreads();
        if (threadIdx.x == 0) g_labmode = bad ? 1 : 0;
    }
    int idx = blockIdx.x * blockDim.x + threadIdx.x;   // 128000 float4s
    if (idx >= NCLS * FDIM / 4) return;
    float4 v = ((const float4*)W)[idx];
    __nv_bfloat162 h0 = __floats2bfloat162_rn(v.x, v.y);
    __nv_bfloat162 h1 = __floats2bfloat162_rn(v.z, v.w);
    uint2 packed;
    packed.x = *(uint32_t*)&h0;
    packed.y = *(uint32_t*)&h1;
    ((uint2*)g_wbf4)[idx] = packed;
}

// ---------------- fused prep + center + bf16 convert: one pass over E ----------------
__global__ void prep_center_kernel(const float* __restrict__ E, const void* __restrict__ labels,
                                   const float* __restrict__ Ctr) {
    int i = blockIdx.x;
    int t = threadIdx.x;    // 128
    __shared__ int slab;
    if (t == 0) {
        int lab;
        if (g_labmode == 0) lab = (int)((const long long*)labels)[i];
        else                lab = ((const int*)labels)[i];
        g_lab[i] = lab;
        slab = lab;
        g_ap[i] = 0u;
        g_an[i] = 0x7f800000u;
    }
    __syncthreads();
    int lab = slab;
    const float4* e4 = (const float4*)(E   + (size_t)i   * FDIM);
    const float4* c4 = (const float4*)(Ctr + (size_t)lab * FDIM);
    float4 v = e4[t];
    float4 cc = c4[t];
    float sq = v.x * v.x + v.y * v.y + v.z * v.z + v.w * v.w;
    float dx = v.x - cc.x, dy = v.y - cc.y, dz = v.z - cc.z, dw = v.w - cc.w;
    float cd = dx * dx + dy * dy + dz * dz + dw * dw;
    __nv_bfloat162 h0 = __floats2bfloat162_rn(v.x, v.y);
    __nv_bfloat162 h1 = __floats2bfloat162_rn(v.z, v.w);
    uint2 packed;
    packed.x = *(uint32_t*)&h0;
    packed.y = *(uint32_t*)&h1;
    ((uint2*)g_ebf4)[(size_t)i * (FDIM / 4) + t] = packed;

    for (int off = 16; off > 0; off >>= 1) {
        sq += __shfl_xor_sync(0xffffffff, sq, off);
        cd += __shfl_xor_sync(0xffffffff, cd, off);
    }
    __shared__ float wsq[4], wcd[4];
    if ((t & 31) == 0) { wsq[t >> 5] = sq; wcd[t >> 5] = cd; }
    __syncthreads();
    if (t == 0) {
        g_sq[i]   = wsq[0] + wsq[1] + wsq[2] + wsq[3];
        g_cent[i] = wcd[0] + wcd[1] + wcd[2] + wcd[3];
    }
}

// ---------------- triplet: symmetric bf16 Gram, ldmatrix, 3-stage pipeline ----------------
__global__ __launch_bounds__(256, 2) void triplet_mma_kernel() {
    extern __shared__ float dynsm[];
    __shared__ float sQi[BM]; __shared__ int sLi[BM];
    __shared__ float sQj[BN]; __shared__ int sLj[BN];

    int rem = blockIdx.x, bi = 0;
    #pragma unroll 1
    for (;;) { int len = NTILE - bi; if (rem < len) break; rem -= len; bi++; }
    int bj = bi + rem;
    bool diag = (bi == bj);

    int t = threadIdx.x;
    int lane = t & 31, wid = t >> 5;
    int wm = wid >> 1, wn = wid & 1;
    int g = lane >> 2, tg = lane & 3;
    int i0 = bi * BM, j0 = bj * BN;

    uint32_t sbase = smem_u32(dynsm);
    const char* ebf = (const char*)g_ebf4;

    uint32_t a_lane = (uint32_t)(((lane & 15) * SSTRW + ((lane >> 4) ? 4 : 0)) * 4);
    uint32_t b_lane = (uint32_t)((((lane & 7) + ((lane >> 4) ? 8 : 0)) * SSTRW + ((lane & 8) ? 4 : 0)) * 4);
    uint32_t aA0 = (uint32_t)(wm * 32 * SSTRW * 4) + a_lane;
    uint32_t aB0 = (uint32_t)((128 + wn * 64) * SSTRW * 4) + b_lane;

    if (t < BM)            { sQi[t] = g_sq[i0 + t]; sLi[t] = g_lab[i0 + t]; }
    else if (t < BM + BN)  { int u = t - BM; sQj[u] = g_sq[j0 + u]; sLj[u] = g_lab[j0 + u]; }

    // prologue: chunks 0,1 -> stages 0,1 (separate groups)
    #pragma unroll
    for (int p = 0; p < 2; p++) {
        uint32_t ab = sbase + p * TSTAGE_BYTES;
        int kof = p * BKT;
        #pragma unroll
        for (int s = 0; s < 8; s++) {
            int f = t + s * 256;
            int row = f >> 3, seg = f & 7;
            int grow = (row < 128) ? (i0 + row) : (j0 + row - 128);
            uint32_t dst = ab + (uint32_t)(row * (SSTRW * 4) + seg * 16);
            cp16(dst, ebf + ((size_t)grow * FDIM + kof + seg * 8) * 2);
        }
        cp_commit();
    }

    float acc[2][8][4];
    #pragma unroll
    for (int mt = 0; mt < 2; mt++)
        #pragma unroll
        for (int nt = 0; nt < 8; nt++)
            #pragma unroll
            for (int e = 0; e < 4; e++) acc[mt][nt][e] = 0.f;

    // 3-stage: chunk c prefetched 2 compute-chunks ahead; wait<1> => chunk c resident.
    #pragma unroll 1
    for (int c = 0; c < NCHT; c++) {
        cp_wait<1>();
        __syncthreads();   // all warps done with stage (c-1)%3 (overwritten by cp(c+2))
        if (c + 2 < NCHT) {
            uint32_t ab = sbase + ((c + 2) % PSTAGES) * TSTAGE_BYTES;
            int kof = (c + 2) * BKT;
            #pragma unroll
            for (int s = 0; s < 8; s++) {
                int f = t + s * 256;
                int row = f >> 3, seg = f & 7;
                int grow = (row < 128) ? (i0 + row) : (j0 + row - 128);
                uint32_t dst = ab + (uint32_t)(row * (SSTRW * 4) + seg * 16);
                cp16(dst, ebf + ((size_t)grow * FDIM + kof + seg * 8) * 2);
            }
        }
        cp_commit();       // empty group in tail keeps group accounting uniform
        uint32_t stg = sbase + (c % PSTAGES) * TSTAGE_BYTES;
        #pragma unroll
        for (int k16 = 0; k16 < 4; k16++) {
            uint32_t w0b = (uint32_t)(k16 * 32);   // 8 words
            uint32_t af[2][4];
            ldsm_x4(af[0][0], af[0][1], af[0][2], af[0][3], stg + aA0 + w0b);
            ldsm_x4(af[1][0], af[1][1], af[1][2], af[1][3], stg + aA0 + 16 * SSTRW * 4 + w0b);
            #pragma unroll
            for (int p = 0; p < 4; p++) {
                uint32_t b0, b1, b2, b3;
                ldsm_x4(b0, b1, b2, b3, stg + aB0 + (uint32_t)(p * 16 * SSTRW * 4) + w0b);
                mma_bf16(acc[0][2 * p    ], af[0], b0, b1);
                mma_bf16(acc[1][2 * p    ], af[1], b0, b1);
                mma_bf16(acc[0][2 * p + 1], af[0], b2, b3);
                mma_bf16(acc[1][2 * p + 1], af[1], b2, b3);
            }
        }
    }

    // ---- dual-sided epilogue ----
    float rap[4], ran[4];
    float cap[16], can[16];
    #pragma unroll
    for (int s4 = 0; s4 < 4; s4++) { rap[s4] = 0.f; ran[s4] = INFINITY; }
    #pragma unroll
    for (int cs = 0; cs < 16; cs++) { cap[cs] = 0.f; can[cs] = INFINITY; }

    #pragma unroll
    for (int mt = 0; mt < 2; mt++) {
        #pragma unroll
        for (int half = 0; half < 2; half++) {
            int lr = wm * 32 + mt * 16 + g + half * 8;
            float qi = sQi[lr]; int li = sLi[lr];
            int slot = mt * 2 + half;
            #pragma unroll
            for (int nt = 0; nt < 8; nt++) {
                #pragma unroll
                for (int e = 0; e < 2; e++) {
                    int lc = wn * 64 + nt * 8 + 2 * tg + e;
                    float d2 = qi + sQj[lc] - 2.f * acc[mt][nt][half * 2 + e];
                    float dist = sqrtf(fmaxf(d2, EPSV));
                    bool same = (sLj[lc] == li);
                    if (same) rap[slot] = fmaxf(rap[slot], dist);
                    else      ran[slot] = fminf(ran[slot], dist);
                    if (!diag) {
                        int cs = nt * 2 + e;
                        if (same) cap[cs] = fmaxf(cap[cs], dist);
                        else      can[cs] = fminf(can[cs], dist);
                    }
                }
            }
        }
    }

    #pragma unroll
    for (int s4 = 0; s4 < 4; s4++) {
        rap[s4] = fmaxf(rap[s4], __shfl_xor_sync(0xffffffff, rap[s4], 1));
        rap[s4] = fmaxf(rap[s4], __shfl_xor_sync(0xffffffff, rap[s4], 2));
        ran[s4] = fminf(ran[s4], __shfl_xor_sync(0xffffffff, ran[s4], 1));
        ran[s4] = fminf(ran[s4], __shfl_xor_sync(0xffffffff, ran[s4], 2));
    }
    if (tg == 0) {
        #pragma unroll
        for (int s4 = 0; s4 < 4; s4++) {
            int lr = wm * 32 + (s4 >> 1) * 16 + g + (s4 & 1) * 8;
            atomicMax(&g_ap[i0 + lr], __float_as_uint(rap[s4]));
            atomicMin(&g_an[i0 + lr], __float_as_uint(ran[s4]));
        }
    }
    if (!diag) {
        #pragma unroll
        for (int cs = 0; cs < 16; cs++) {
            cap[cs] = fmaxf(cap[cs], __shfl_xor_sync(0xffffffff, cap[cs], 4));
            cap[cs] = fmaxf(cap[cs], __shfl_xor_sync(0xffffffff, cap[cs], 8));
            cap[cs] = fmaxf(cap[cs], __shfl_xor_sync(0xffffffff, cap[cs], 16));
            can[cs] = fminf(can[cs], __shfl_xor_sync(0xffffffff, can[cs], 4));
            can[cs] = fminf(can[cs], __shfl_xor_sync(0xffffffff, can[cs], 8));
            can[cs] = fminf(can[cs], __shfl_xor_sync(0xffffffff, can[cs], 16));
        }
        if (lane < 4) {
            #pragma unroll
            for (int cs = 0; cs < 16; cs++) {
                int col = j0 + wn * 64 + (cs >> 1) * 8 + 2 * lane + (cs & 1);
                atomicMax(&g_ap[col], __float_as_uint(cap[cs]));
                atomicMin(&g_an[col], __float_as_uint(can[cs]));
            }
        }
    }
}

// ---------------- CE: bf16 logits, ldmatrix, 3-stage pipeline ----------------
__global__ __launch_bounds__(256, 2) void ce_mma_kernel(const float* __restrict__ bvec) {
    extern __shared__ float dynsm[];
    __shared__ float sBias[BN];
    __shared__ int   sLab[BM];

    int t = threadIdx.x;
    int lane = t & 31, wid = t >> 5;
    int wm = wid >> 1, wn = wid & 1;
    int g = lane >> 2, tg = lane & 3;
    int i0 = blockIdx.x * BM, j0 = blockIdx.y * BN;
    int jt = blockIdx.y;

    uint32_t sbase = smem_u32(dynsm);
    const char* ebf = (const char*)g_ebf4;
    const char* wbf = (const char*)g_wbf4;

    uint32_t a_lane = (uint32_t)(((lane & 15) * SSTRW + ((lane >> 4) ? 4 : 0)) * 4);
    uint32_t b_lane = (uint32_t)((((lane & 7) + ((lane >> 4) ? 8 : 0)) * SSTRW + ((lane & 8) ? 4 : 0)) * 4);
    uint32_t aA0 = (uint32_t)(wm * 32 * SSTRW * 4) + a_lane;
    uint32_t aB0 = (uint32_t)((128 + wn * 64) * SSTRW * 4) + b_lane;

    if (t < BN)           { int cls = j0 + t; sBias[t] = bvec[cls < NCLS ? cls : NCLS - 1]; }
    else if (t < BN + BM) { sLab[t - BN] = g_lab[i0 + (t - BN)]; }

    #pragma unroll
    for (int p = 0; p < 2; p++) {
        uint32_t ab = sbase + p * TSTAGE_BYTES;
        int kof = p * BKT;
        #pragma unroll
        for (int s = 0; s < 8; s++) {
            int f = t + s * 256;
            int row = f >> 3, seg = f & 7;
            uint32_t dst = ab + (uint32_t)(row * (SSTRW * 4) + seg * 16);
            if (row < 128) {
                cp16(dst, ebf + ((size_t)(i0 + row) * FDIM + kof + seg * 8) * 2);
            } else {
                int wr = j0 + row - 128; if (wr >= NCLS) wr = NCLS - 1;
                cp16(dst, wbf + ((size_t)wr * FDIM + kof + seg * 8) * 2);
            }
        }
        cp_commit();
    }

    float acc[2][8][4];
    #pragma unroll
    for (int mt = 0; mt < 2; mt++)
        #pragma unroll
        for (int nt = 0; nt < 8; nt++)
            #pragma unroll
            for (int e = 0; e < 4; e++) acc[mt][nt][e] = 0.f;

    #pragma unroll 1
    for (int c = 0; c < NCHT; c++) {
        cp_wait<1>();
        __syncthreads();
        if (c + 2 < NCHT) {
            uint32_t ab = sbase + ((c + 2) % PSTAGES) * TSTAGE_BYTES;
            int kof = (c + 2) * BKT;
            #pragma unroll
            for (int s = 0; s < 8; s++) {
                int f = t + s * 256;
                int row = f >> 3, seg = f & 7;
                uint32_t dst = ab + (uint32_t)(row * (SSTRW * 4) + seg * 16);
                if (row < 128) {
                    cp16(dst, ebf + ((size_t)(i0 + row) * FDIM + kof + seg * 8) * 2);
                } else {
                    int wr = j0 + row - 128; if (wr >= NCLS) wr = NCLS - 1;
                    cp16(dst, wbf + ((size_t)wr * FDIM + kof + seg * 8) * 2);
                }
            }
        }
        cp_commit();
        uint32_t stg = sbase + (c % PSTAGES) * TSTAGE_BYTES;
        #pragma unroll
        for (int k16 = 0; k16 < 4; k16++) {
            uint32_t w0b = (uint32_t)(k16 * 32);
            uint32_t af[2][4];
            ldsm_x4(af[0][0], af[0][1], af[0][2], af[0][3], stg + aA0 + w0b);
            ldsm_x4(af[1][0], af[1][1], af[1][2], af[1][3], stg + aA0 + 16 * SSTRW * 4 + w0b);
            #pragma unroll
            for (int p = 0; p < 4; p++) {
                uint32_t b0, b1, b2, b3;
                ldsm_x4(b0, b1, b2, b3, stg + aB0 + (uint32_t)(p * 16 * SSTRW * 4) + w0b);
                mma_bf16(acc[0][2 * p    ], af[0], b0, b1);
                mma_bf16(acc[1][2 * p    ], af[1], b0, b1);
                mma_bf16(acc[0][2 * p + 1], af[0], b2, b3);
                mma_bf16(acc[1][2 * p + 1], af[1], b2, b3);
            }
        }
    }

    // epilogue: masked bias-add, per-(row, warp-half) partial (max, sumexp)
    #pragma unroll
    for (int mt = 0; mt < 2; mt++) {
        #pragma unroll
        for (int half = 0; half < 2; half++) {
            int lr = wm * 32 + mt * 16 + g + half * 8;
            int irow = i0 + lr;
            int lab  = sLab[lr];
            float v[16];
            float m = -INFINITY;
            #pragma unroll
            for (int nt = 0; nt < 8; nt++) {
                #pragma unroll
                for (int e = 0; e < 2; e++) {
                    int lc  = wn * 64 + nt * 8 + 2 * tg + e;
                    int col = j0 + lc;
                    float x = (col < NCLS) ? (acc[mt][nt][half * 2 + e] + sBias[lc]) : -INFINITY;
                    if (col == lab) g_ref[irow] = x;
                    v[nt * 2 + e] = x;
                    m = fmaxf(m, x);
                }
            }
            m = fmaxf(m, __shfl_xor_sync(0xffffffff, m, 1));
            m = fmaxf(m, __shfl_xor_sync(0xffffffff, m, 2));
            float s = 0.f;
            #pragma unroll
            for (int q = 0; q < 16; q++) s += __expf(v[q] - m);
            s += __shfl_xor_sync(0xffffffff, s, 1);
            s += __shfl_xor_sync(0xffffffff, s, 2);
            if (tg == 0) { g_pm[irow][jt * 2 + wn] = m; g_ps[irow][jt * 2 + wn] = s; }
        }
    }
}

// ---------------- final: CE merge + total loss (deterministic) ----------------
__global__ void final_kernel(float* __restrict__ out) {
    int t = threadIdx.x;   // 1024
    float l = 0.f;
    for (int i = t; i < BATCH; i += 1024) {
        float M = -INFINITY;
        #pragma unroll
        for (int k = 0; k < NJT2; k++) M = fmaxf(M, g_pm[i][k]);
        float S = 0.f;
        #pragma unroll
        for (int k = 0; k < NJT2; k++) S += g_ps[i][k] * expf(g_pm[i][k] - M);
        float ce = M + logf(S) - g_ref[i];
        float ap = __uint_as_float(g_ap[i]);
        float an = __uint_as_float(g_an[i]);
        l += fmaxf(ap - an + MARGIN, 0.f) + LAMBDA * g_cent[i] + ce;
    }
    __shared__ float red[1024];
    red[t] = l;
    __syncthreads();
    for (int off = 512; off > 0; off >>= 1) {
        if (t < off) red[t] += red[t + off];
        __syncthreads();
    }
    if (t == 0) out[0] = red[0] / (float)BATCH;
}

// ---------------- launch ----------------
extern "C" void kernel_launch(void* const* d_in, const int* in_sizes, int n_in,
                              void* d_out, int out_size) {
    const float* E    = (const float*)d_in[0];
    const void*  labs = d_in[1];
    const float* Ctr  = (const float*)d_in[2];
    const float* W    = (const float*)d_in[3];
    const float* bvec = (const float*)d_in[4];
    float* out = (float*)d_out;

    cudaFuncSetAttribute(triplet_mma_kernel, cudaFuncAttributeMaxDynamicSharedMemorySize, TDYN_BYTES);
    cudaFuncSetAttribute(ce_mma_kernel,      cudaFuncAttributeMaxDynamicSharedMemorySize, TDYN_BYTES);

    detect_wconv_kernel<<<(NCLS * FDIM / 4 + 255) / 256, 256>>>((const long long*)labs, W);
    prep_center_kernel<<<BATCH, 128>>>(E, labs, Ctr);
    triplet_mma_kernel<<<NTRI, 256, TDYN_BYTES>>>();
    ce_mma_kernel<<<dim3(BATCH / BM, 1024 / BN), 256, TDYN_BYTES>>>(bvec);
    final_kernel<<<1, 1024>>>(out);
}